// round 12
// baseline (speedup 1.0000x reference)
#include <cuda_runtime.h>
#include <math.h>

#define BB 64
#define TT 512
#define HH 768
#define LL 32
#define MID 256

// Scratch (static device globals: no allocation allowed)
__device__ float d_em[BB * TT * LL];    // emissions (log domain), 4 MB
__device__ float d_part[BB];            // per-batch (denom - numer)
__device__ int   d_ctr = 0;             // ticket counter for final reduce

typedef unsigned long long ull;

// ---- packed f32x2 helpers (Blackwell, PTX-only) ----
__device__ __forceinline__ ull pk2(float a, float b) {
    ull r;
    asm("mov.b64 %0, {%1, %2};" : "=l"(r) : "f"(a), "f"(b));
    return r;
}
__device__ __forceinline__ void upk2(ull v, float& a, float& b) {
    asm("mov.b64 {%0, %1}, %2;" : "=f"(a), "=f"(b) : "l"(v));
}
__device__ __forceinline__ ull f2fma(ull a, ull b, ull c) {
    ull d;
    asm("fma.rn.f32x2 %0, %1, %2, %3;" : "=l"(d) : "l"(a), "l"(b), "l"(c));
    return d;
}
__device__ __forceinline__ ull f2add(ull a, ull b) {
    ull d;
    asm("add.rn.f32x2 %0, %1, %2;" : "=l"(d) : "l"(a), "l"(b));
    return d;
}
__device__ __forceinline__ float frcp(float x) {
    float r;
    asm("rcp.approx.f32 %0, %1;" : "=f"(r) : "f"(x));
    return r;
}
#define MBAR() asm volatile("bar.sync 1, 96;" ::: "memory")

// ============================================================
// Kernel 1: emissions = hidden_states @ W + b  (R5-exact 57.9us)
// ============================================================
#define KC 16
__global__ __launch_bounds__(128) void gemm_k(const float* __restrict__ hs,
                                              const float* __restrict__ W,
                                              const float* __restrict__ bias) {
    __shared__ float hsh[KC][128];
    __shared__ float wsh[KC][32];
    const int tid = threadIdx.x;
    const int rowBase = blockIdx.x * 128;
    const int tr = tid >> 3, tc = tid & 7;
    const int r0 = tr * 8, c0 = tc * 4;

    ull acc[8][2];
    {
        float4 bb = *reinterpret_cast<const float4*>(bias + c0);
#pragma unroll
        for (int r = 0; r < 8; r++) {
            acc[r][0] = pk2(bb.x, bb.y);
            acc[r][1] = pk2(bb.z, bb.w);
        }
    }

    float4 hld[4];
    float  wld[4];

#pragma unroll
    for (int i = 0; i < 4; i++) {
        int idx = tid + i * 128;
        int row = idx >> 2, kq = idx & 3;
        hld[i] = *reinterpret_cast<const float4*>(hs + (size_t)(rowBase + row) * HH + kq * 4);
    }
#pragma unroll
    for (int i = 0; i < 4; i++) {
        int idx = tid + i * 128;
        wld[i] = W[(idx >> 5) * LL + (idx & 31)];
    }

    const int NCH = HH / KC;  // 48
    for (int ch = 0; ch < NCH; ch++) {
        __syncthreads();
#pragma unroll
        for (int i = 0; i < 4; i++) {
            int idx = tid + i * 128;
            int row = idx >> 2, kq = idx & 3;
            hsh[kq * 4 + 0][row] = hld[i].x;
            hsh[kq * 4 + 1][row] = hld[i].y;
            hsh[kq * 4 + 2][row] = hld[i].z;
            hsh[kq * 4 + 3][row] = hld[i].w;
        }
#pragma unroll
        for (int i = 0; i < 4; i++) {
            int idx = tid + i * 128;
            wsh[idx >> 5][idx & 31] = wld[i];
        }
        __syncthreads();

        if (ch + 1 < NCH) {
            int k0 = (ch + 1) * KC;
#pragma unroll
            for (int i = 0; i < 4; i++) {
                int idx = tid + i * 128;
                int row = idx >> 2, kq = idx & 3;
                hld[i] = *reinterpret_cast<const float4*>(hs + (size_t)(rowBase + row) * HH + k0 + kq * 4);
            }
#pragma unroll
            for (int i = 0; i < 4; i++) {
                int idx = tid + i * 128;
                wld[i] = W[(k0 + (idx >> 5)) * LL + (idx & 31)];
            }
        }

#pragma unroll
        for (int kk = 0; kk < KC; kk++) {
            float4 h0 = *reinterpret_cast<const float4*>(&hsh[kk][r0]);
            float4 h1 = *reinterpret_cast<const float4*>(&hsh[kk][r0 + 4]);
            float4 w0 = *reinterpret_cast<const float4*>(&wsh[kk][c0]);
            ull wp0 = pk2(w0.x, w0.y);
            ull wp1 = pk2(w0.z, w0.w);
            float hv[8] = {h0.x, h0.y, h0.z, h0.w, h1.x, h1.y, h1.z, h1.w};
#pragma unroll
            for (int r = 0; r < 8; r++) {
                ull hv2 = pk2(hv[r], hv[r]);
                acc[r][0] = f2fma(hv2, wp0, acc[r][0]);
                acc[r][1] = f2fma(hv2, wp1, acc[r][1]);
            }
        }
    }

#pragma unroll
    for (int r = 0; r < 8; r++) {
        float a[4];
        upk2(acc[r][0], a[0], a[1]);
        upk2(acc[r][1], a[2], a[3]);
        size_t base = (size_t)(rowBase + r0 + r) * LL + c0;
        *reinterpret_cast<float4*>(d_em + base) = make_float4(a[0], a[1], a[2], a[3]);
    }
}

// ============================================================
// Kernel 2: CRF per batch. 1 block/batch, 3 warps (R5 logic),
// two-phase barrier schedule (NO spinning):
//   phase1: w0 fwd t<MID | w1 vit t<MID | w2 numerator
//   [bar 1,96]
//   phase2: w0 fwd rest  | w1 vit rest  | w2 hist[1..MID) via
//           bit-exact ballot matching (reads phase-1 bestv)
//   [syncthreads]
//   w0: hybrid backtrace (ballot for t>=MID, u8 chase below)
//   w1/w2: PAD tail zero-fill; w1 lane0: loss ticket reduce
// ============================================================
#define OFF_EMS   0
#define OFF_BESTV (512 * 32)
#define OFF_TRS   (2 * 512 * 32)
#define OFF_VSHF  (OFF_TRS + 32 * 33)
#define OFF_VSHV  (OFF_VSHF + 64)
#define OFF_HIST  (OFF_VSHV + 64)
#define CRF_SMEM_FLOATS (OFF_HIST + 512 * 32 / 4)

__global__ __launch_bounds__(96) void crf_k(const int* __restrict__ attn,
                                            const int* __restrict__ labels,
                                            const float* __restrict__ startT,
                                            const float* __restrict__ endT,
                                            const float* __restrict__ trans,
                                            float* __restrict__ out) {
    extern __shared__ float sm[];
    float* emS   = sm + OFF_EMS;
    float* bestv = sm + OFF_BESTV;
    float* trS   = sm + OFF_TRS;
    float* vshF  = sm + OFF_VSHF;
    float* vshV  = sm + OFF_VSHV;
    unsigned char* histS = reinterpret_cast<unsigned char*>(sm + OFF_HIST);
    __shared__ float sh_denom, sh_numer;
    __shared__ int sh_best;

    const int b = blockIdx.x;
    const int tid = threadIdx.x;
    const int w = tid >> 5, lane = tid & 31;
    const unsigned F = 0xffffffffu;

    // ---- preload emissions tile (64 KB) + transitions ----
    {
        const float4* src = reinterpret_cast<const float4*>(d_em + (size_t)b * TT * LL);
        float4* dst = reinterpret_cast<float4*>(emS);
#pragma unroll 4
        for (int i = tid; i < TT * LL / 4; i += 96) dst[i] = src[i];
        for (int idx = tid; idx < LL * LL; idx += 96)
            trS[(idx >> 5) * 33 + (idx & 31)] = trans[idx];
    }

    // sequence length (prefix mask) — per warp
    int len = 0;
    {
        const int* am = attn + b * TT;
        for (int tt = lane; tt < TT; tt += 32) len += am[tt];
#pragma unroll
        for (int o = 16; o; o >>= 1) len += __shfl_xor_sync(F, len, o);
    }
    __syncthreads();

    const int P1 = (len < MID) ? len : MID;

    if (w == 0) {
        // ---------------- forward recursion (R5-exact steps) ----------------
        ull Et2[16];
#pragma unroll
        for (int q = 0; q < 16; q++)
            Et2[q] = pk2(__expf(trans[(2 * q) * LL + lane]),
                         __expf(trans[(2 * q + 1) * LL + lane]));
        float sc0 = startT[lane] + emS[lane];
        float ref0 = __shfl_sync(F, sc0, 0);
        float u = __expf(sc0 - ref0);
        float c = ref0;
        vshF[lane] = u;
        __syncwarp();

        for (int half = 0; half < 2; half++) {
            const int t0 = half ? P1 : 1;
            const int t1 = half ? len : P1;
            for (int t = t0; t < t1; t++) {
                float ext = __expf(emS[t * 32 + lane]);
                const ulonglong2* u2p =
                    reinterpret_cast<const ulonglong2*>(&vshF[((t - 1) & 1) * 32]);
                ull s0 = 0, s1 = 0, s2 = 0, s3 = 0;
#pragma unroll
                for (int q = 0; q < 8; q += 2) {
                    ulonglong2 ua = u2p[q];
                    ulonglong2 ub = u2p[q + 1];
                    s0 = f2fma(ua.x, Et2[2 * q], s0);
                    s1 = f2fma(ua.y, Et2[2 * q + 1], s1);
                    s2 = f2fma(ub.x, Et2[2 * q + 2], s2);
                    s3 = f2fma(ub.y, Et2[2 * q + 3], s3);
                }
                float a0, a1, a2, a3, a4, a5, a6, a7;
                upk2(s0, a0, a1); upk2(s1, a2, a3);
                upk2(s2, a4, a5); upk2(s3, a6, a7);
                u = ext * (((a0 + a1) + (a2 + a3)) + ((a4 + a5) + (a6 + a7)));
                if ((t & 7) == 0) {
                    float r = __shfl_sync(F, u, 0);
                    u *= frcp(r);
                    c += __logf(r);
                }
                vshF[(t & 1) * 32 + lane] = u;
                __syncwarp();
            }
            if (half == 0) MBAR();
        }
        float v = u * __expf(endT[lane]);
#pragma unroll
        for (int o = 16; o; o >>= 1) v += __shfl_xor_sync(F, v, o);
        if (lane == 0) sh_denom = c + __logf(v);
    } else if (w == 1) {
        // ---------------- Viterbi recursion (R5-exact steps) ----------------
        ull tr2[16];
#pragma unroll
        for (int q = 0; q < 16; q++)
            tr2[q] = pk2(trans[(2 * q) * LL + lane],
                         trans[(2 * q + 1) * LL + lane]);
        float vs = startT[lane] + emS[lane];
        vshV[lane] = vs;
        __syncwarp();

        for (int half = 0; half < 2; half++) {
            const int t0 = half ? P1 : 1;
            const int t1 = half ? len : P1;
            for (int t = t0; t < t1; t++) {
                float emt = emS[t * 32 + lane];
                const ulonglong2* v2p =
                    reinterpret_cast<const ulonglong2*>(&vshV[((t - 1) & 1) * 32]);
                float m[8];
#pragma unroll
                for (int q = 0; q < 8; q++) {
                    ulonglong2 uu = v2p[q];
                    ull c01 = f2add(uu.x, tr2[2 * q]);
                    ull c23 = f2add(uu.y, tr2[2 * q + 1]);
                    float c0, c1, c2, c3;
                    upk2(c01, c0, c1);
                    upk2(c23, c2, c3);
                    m[q] = fmaxf(fmaxf(c0, c1), fmaxf(c2, c3));
                }
                float best = fmaxf(fmaxf(fmaxf(m[0], m[1]), fmaxf(m[2], m[3])),
                                   fmaxf(fmaxf(m[4], m[5]), fmaxf(m[6], m[7])));
                bestv[t * 32 + lane] = best;
                vs = best + emt;
                vshV[(t & 1) * 32 + lane] = vs;
                __syncwarp();
            }
            if (half == 0) MBAR();
        }
        float v = vs + endT[lane];
        int idx = lane;
#pragma unroll
        for (int o = 16; o; o >>= 1) {
            float ov = __shfl_xor_sync(F, v, o);
            int oi = __shfl_xor_sync(F, idx, o);
            if (ov > v || (ov == v && oi < idx)) { v = ov; idx = oi; }
        }
        if (lane == 0) sh_best = idx;
    } else {
        // ---- phase 1: numerator ----
        const int* lab = labels + b * TT;
        float part = 0.f;
        for (int t = 1 + lane; t < TT; t += 32) {
            if (t < len) {
                int lt = lab[t], lp = lab[t - 1];
                part += emS[t * 32 + lt] + trS[lp * 33 + lt];
            }
        }
#pragma unroll
        for (int o = 16; o; o >>= 1) part += __shfl_xor_sync(F, part, o);
        if (lane == 0) {
            int l0 = lab[0];
            int llast = lab[len - 1];
            part += startT[l0] + emS[l0] + endT[llast];
            sh_numer = part;
        }
        MBAR();
        // ---- phase 2: hist precompute for t in [1, P1) (bit-exact) ----
        float st_l = startT[lane];
        for (int t = 1; t < P1; t++) {
            float vsp = ((t - 1 == 0) ? st_l : bestv[(t - 1) * 32 + lane]) +
                        emS[(t - 1) * 32 + lane];
#pragma unroll 8
            for (int j = 0; j < 32; j++) {
                float trv = trS[lane * 33 + j];
                float tgt = bestv[t * 32 + j];
                unsigned mk = __ballot_sync(F, (vsp + trv) == tgt);
                if (lane == 0) histS[t * 32 + j] = (unsigned char)(__ffs(mk) - 1);
            }
        }
    }
    __syncthreads();

    // ------------------------- outputs -------------------------
    const int last_idx = len - 1;
    float* pred = out + 1 + (size_t)b * TT;
    if (w == 0) {
        const int bestl = sh_best;
        if (lane == 0) pred[last_idx] = (float)bestl;
        int carry = bestl;
        int t = last_idx;
        // ballot-chase for t >= P1 (bestv-only region)
        if (t >= P1) {
            float st_l = startT[lane];
            float vsp_next = ((t - 1 == 0) ? st_l : bestv[(t - 1) * 32 + lane]) +
                             emS[(t - 1) * 32 + lane];
            for (; t >= P1; t--) {
                float vsp = vsp_next;
                if (t >= 2) {
                    int tm2 = t - 2;
                    vsp_next = ((tm2 == 0) ? st_l : bestv[tm2 * 32 + lane]) +
                               emS[tm2 * 32 + lane];
                }
                float trv = trS[lane * 33 + carry];
                float tgt = bestv[t * 32 + carry];
                unsigned mk = __ballot_sync(F, (vsp + trv) == tgt);
                int prev = __ffs(mk) - 1;
                if (lane == 0) pred[t - 1] = (float)prev;
                carry = prev;
            }
        }
        // u8 pointer-chase for t < P1 (precomputed hist)
        for (; t >= 1; t--) {
            carry = histS[t * 32 + carry];
            if (lane == 0) pred[t - 1] = (float)carry;
        }
    } else {
        for (int tt = last_idx + 1 + (tid - 32); tt < TT; tt += 64)
            pred[tt] = 0.0f;
        if (w == 1 && lane == 0) {
            d_part[b] = sh_denom - sh_numer;
            __threadfence();
            int old = atomicAdd(&d_ctr, 1);
            if (old == BB - 1) {
                __threadfence();
                float v = 0.f;   // deterministic fixed-order reduce
#pragma unroll
                for (int i = 0; i < BB; i++) v += d_part[i];
                out[0] = v;
                d_ctr = 0;       // reset for graph replay
            }
        }
    }
}

extern "C" void kernel_launch(void* const* d_in, const int* in_sizes, int n_in,
                              void* d_out, int out_size) {
    (void)in_sizes; (void)n_in; (void)out_size;
    const float* hs     = (const float*)d_in[0];
    const int*   attn   = (const int*)d_in[1];
    const int*   labels = (const int*)d_in[2];
    const float* W      = (const float*)d_in[3];
    const float* bias   = (const float*)d_in[4];
    const float* startT = (const float*)d_in[5];
    const float* endT   = (const float*)d_in[6];
    const float* trans  = (const float*)d_in[7];
    float* out = (float*)d_out;

    const int crf_smem = CRF_SMEM_FLOATS * sizeof(float);  // ~152 KB
    cudaFuncSetAttribute(crf_k, cudaFuncAttributeMaxDynamicSharedMemorySize, crf_smem);

    gemm_k<<<(BB * TT) / 128, 128>>>(hs, W, bias);
    crf_k<<<BB, 96, crf_smem>>>(attn, labels, startT, endT, trans, out);
}

// round 13
// speedup vs baseline: 4.0292x; 4.0292x over previous
#include <cuda_runtime.h>
#include <math.h>

#define BB 64
#define TT 512
#define HH 768
#define LL 32

// Scratch (static device globals: no allocation allowed)
__device__ float d_em[BB * TT * LL];    // emissions (log domain), 4 MB
__device__ float d_part[BB];            // per-batch (denom - numer)
__device__ int   d_ctr = 0;             // ticket counter for final reduce

typedef unsigned long long ull;

// ---- packed f32x2 helpers (Blackwell, PTX-only) ----
__device__ __forceinline__ ull pk2(float a, float b) {
    ull r;
    asm("mov.b64 %0, {%1, %2};" : "=l"(r) : "f"(a), "f"(b));
    return r;
}
__device__ __forceinline__ void upk2(ull v, float& a, float& b) {
    asm("mov.b64 {%0, %1}, %2;" : "=f"(a), "=f"(b) : "l"(v));
}
__device__ __forceinline__ ull f2fma(ull a, ull b, ull c) {
    ull d;
    asm("fma.rn.f32x2 %0, %1, %2, %3;" : "=l"(d) : "l"(a), "l"(b), "l"(c));
    return d;
}
__device__ __forceinline__ ull f2add(ull a, ull b) {
    ull d;
    asm("add.rn.f32x2 %0, %1, %2;" : "=l"(d) : "l"(a), "l"(b));
    return d;
}
__device__ __forceinline__ float frcp(float x) {
    float r;
    asm("rcp.approx.f32 %0, %1;" : "=f"(r) : "f"(x));
    return r;
}

// ============================================================
// Kernel 1: emissions = hidden_states @ W + b  (R5-exact)
// ============================================================
#define KC 16
__global__ __launch_bounds__(128) void gemm_k(const float* __restrict__ hs,
                                              const float* __restrict__ W,
                                              const float* __restrict__ bias) {
    __shared__ float hsh[KC][128];
    __shared__ float wsh[KC][32];
    const int tid = threadIdx.x;
    const int rowBase = blockIdx.x * 128;
    const int tr = tid >> 3, tc = tid & 7;
    const int r0 = tr * 8, c0 = tc * 4;

    ull acc[8][2];
    {
        float4 bb = *reinterpret_cast<const float4*>(bias + c0);
#pragma unroll
        for (int r = 0; r < 8; r++) {
            acc[r][0] = pk2(bb.x, bb.y);
            acc[r][1] = pk2(bb.z, bb.w);
        }
    }

    float4 hld[4];
    float  wld[4];

#pragma unroll
    for (int i = 0; i < 4; i++) {
        int idx = tid + i * 128;
        int row = idx >> 2, kq = idx & 3;
        hld[i] = *reinterpret_cast<const float4*>(hs + (size_t)(rowBase + row) * HH + kq * 4);
    }
#pragma unroll
    for (int i = 0; i < 4; i++) {
        int idx = tid + i * 128;
        wld[i] = W[(idx >> 5) * LL + (idx & 31)];
    }

    const int NCH = HH / KC;  // 48
    for (int ch = 0; ch < NCH; ch++) {
        __syncthreads();
#pragma unroll
        for (int i = 0; i < 4; i++) {
            int idx = tid + i * 128;
            int row = idx >> 2, kq = idx & 3;
            hsh[kq * 4 + 0][row] = hld[i].x;
            hsh[kq * 4 + 1][row] = hld[i].y;
            hsh[kq * 4 + 2][row] = hld[i].z;
            hsh[kq * 4 + 3][row] = hld[i].w;
        }
#pragma unroll
        for (int i = 0; i < 4; i++) {
            int idx = tid + i * 128;
            wsh[idx >> 5][idx & 31] = wld[i];
        }
        __syncthreads();

        if (ch + 1 < NCH) {
            int k0 = (ch + 1) * KC;
#pragma unroll
            for (int i = 0; i < 4; i++) {
                int idx = tid + i * 128;
                int row = idx >> 2, kq = idx & 3;
                hld[i] = *reinterpret_cast<const float4*>(hs + (size_t)(rowBase + row) * HH + k0 + kq * 4);
            }
#pragma unroll
            for (int i = 0; i < 4; i++) {
                int idx = tid + i * 128;
                wld[i] = W[(k0 + (idx >> 5)) * LL + (idx & 31)];
            }
        }

#pragma unroll
        for (int kk = 0; kk < KC; kk++) {
            float4 h0 = *reinterpret_cast<const float4*>(&hsh[kk][r0]);
            float4 h1 = *reinterpret_cast<const float4*>(&hsh[kk][r0 + 4]);
            float4 w0 = *reinterpret_cast<const float4*>(&wsh[kk][c0]);
            ull wp0 = pk2(w0.x, w0.y);
            ull wp1 = pk2(w0.z, w0.w);
            float hv[8] = {h0.x, h0.y, h0.z, h0.w, h1.x, h1.y, h1.z, h1.w};
#pragma unroll
            for (int r = 0; r < 8; r++) {
                ull hv2 = pk2(hv[r], hv[r]);
                acc[r][0] = f2fma(hv2, wp0, acc[r][0]);
                acc[r][1] = f2fma(hv2, wp1, acc[r][1]);
            }
        }
    }

#pragma unroll
    for (int r = 0; r < 8; r++) {
        float a[4];
        upk2(acc[r][0], a[0], a[1]);
        upk2(acc[r][1], a[2], a[3]);
        size_t base = (size_t)(rowBase + r0 + r) * LL + c0;
        *reinterpret_cast<float4*>(d_em + base) = make_float4(a[0], a[1], a[2], a[3]);
    }
}

// ============================================================
// Kernel 2: CRF per batch (R5-exact), 1 block/batch, 3 warps:
//   warp0: forward (linear-domain) -> denom, then backtrace
//   warp1: Viterbi (max only) -> best_last
//   warp2: numerator
// Only change vs R5: loss ticket-reduce folded in (no fin_k).
// ============================================================
#define OFF_EMS   0
#define OFF_BESTV (512 * 32)
#define OFF_TRS   (2 * 512 * 32)
#define OFF_VSH   (2 * 512 * 32 + 32 * 33)
#define CRF_SMEM_FLOATS (OFF_VSH + 128)

__global__ __launch_bounds__(96) void crf_k(const int* __restrict__ attn,
                                            const int* __restrict__ labels,
                                            const float* __restrict__ startT,
                                            const float* __restrict__ endT,
                                            const float* __restrict__ trans,
                                            float* __restrict__ out) {
    extern __shared__ float sm[];
    float* emS   = sm + OFF_EMS;
    float* bestv = sm + OFF_BESTV;
    float* trS   = sm + OFF_TRS;
    float* vshF  = sm + OFF_VSH;
    float* vshV  = sm + OFF_VSH + 64;
    __shared__ float sh_denom, sh_numer;
    __shared__ int sh_best;

    const int b = blockIdx.x;
    const int tid = threadIdx.x;
    const int w = tid >> 5, lane = tid & 31;
    const unsigned F = 0xffffffffu;

    // ---- preload emissions tile (64 KB) + transitions ----
    {
        const float4* src = reinterpret_cast<const float4*>(d_em + (size_t)b * TT * LL);
        float4* dst = reinterpret_cast<float4*>(emS);
#pragma unroll 4
        for (int i = tid; i < TT * LL / 4; i += 96) dst[i] = src[i];
        for (int idx = tid; idx < LL * LL; idx += 96)
            trS[(idx >> 5) * 33 + (idx & 31)] = trans[idx];
    }

    // sequence length (prefix mask)
    int len = 0;
    {
        const int* am = attn + b * TT;
        for (int tt = lane; tt < TT; tt += 32) len += am[tt];
#pragma unroll
        for (int o = 16; o; o >>= 1) len += __shfl_xor_sync(F, len, o);
    }
    __syncthreads();

    if (w == 0) {
        // -------- forward recursion, linear domain --------
        ull Et2[16];
#pragma unroll
        for (int q = 0; q < 16; q++)
            Et2[q] = pk2(__expf(trans[(2 * q) * LL + lane]),
                         __expf(trans[(2 * q + 1) * LL + lane]));
        float sc0 = startT[lane] + emS[lane];
        float ref0 = __shfl_sync(F, sc0, 0);
        float u = __expf(sc0 - ref0);
        float c = ref0;

        vshF[lane] = u;
        __syncwarp();

        for (int t = 1; t < len; t++) {
            float ext = __expf(emS[t * 32 + lane]);

            const ulonglong2* u2p =
                reinterpret_cast<const ulonglong2*>(&vshF[((t - 1) & 1) * 32]);
            ull s0 = 0, s1 = 0, s2 = 0, s3 = 0;
#pragma unroll
            for (int q = 0; q < 8; q += 2) {
                ulonglong2 ua = u2p[q];
                ulonglong2 ub = u2p[q + 1];
                s0 = f2fma(ua.x, Et2[2 * q], s0);
                s1 = f2fma(ua.y, Et2[2 * q + 1], s1);
                s2 = f2fma(ub.x, Et2[2 * q + 2], s2);
                s3 = f2fma(ub.y, Et2[2 * q + 3], s3);
            }
            float a0, a1, a2, a3, a4, a5, a6, a7;
            upk2(s0, a0, a1); upk2(s1, a2, a3);
            upk2(s2, a4, a5); upk2(s3, a6, a7);
            u = ext * (((a0 + a1) + (a2 + a3)) + ((a4 + a5) + (a6 + a7)));

            if ((t & 7) == 0) {
                float r = __shfl_sync(F, u, 0);
                u *= frcp(r);
                c += __logf(r);
            }
            vshF[(t & 1) * 32 + lane] = u;
            __syncwarp();
        }
        float v = u * __expf(endT[lane]);
#pragma unroll
        for (int o = 16; o; o >>= 1) v += __shfl_xor_sync(F, v, o);
        if (lane == 0) sh_denom = c + __logf(v);
    } else if (w == 1) {
        // -------- Viterbi: max only (argmax deferred to backtrace) --------
        ull tr2[16];
#pragma unroll
        for (int q = 0; q < 16; q++)
            tr2[q] = pk2(trans[(2 * q) * LL + lane], trans[(2 * q + 1) * LL + lane]);
        float vs = startT[lane] + emS[lane];
        vshV[lane] = vs;
        __syncwarp();

        for (int t = 1; t < len; t++) {
            float emt = emS[t * 32 + lane];

            const ulonglong2* v2p =
                reinterpret_cast<const ulonglong2*>(&vshV[((t - 1) & 1) * 32]);
            float m[8];
#pragma unroll
            for (int q = 0; q < 8; q++) {
                ulonglong2 uu = v2p[q];
                ull c01 = f2add(uu.x, tr2[2 * q]);
                ull c23 = f2add(uu.y, tr2[2 * q + 1]);
                float c0, c1, c2, c3;
                upk2(c01, c0, c1);
                upk2(c23, c2, c3);
                m[q] = fmaxf(fmaxf(c0, c1), fmaxf(c2, c3));
            }
            float best = fmaxf(fmaxf(fmaxf(m[0], m[1]), fmaxf(m[2], m[3])),
                               fmaxf(fmaxf(m[4], m[5]), fmaxf(m[6], m[7])));
            bestv[t * 32 + lane] = best;
            vs = best + emt;
            vshV[(t & 1) * 32 + lane] = vs;
            __syncwarp();
        }
        float v = vs + endT[lane];
        int idx = lane;
#pragma unroll
        for (int o = 16; o; o >>= 1) {
            float ov = __shfl_xor_sync(F, v, o);
            int oi = __shfl_xor_sync(F, idx, o);
            if (ov > v || (ov == v && oi < idx)) { v = ov; idx = oi; }
        }
        if (lane == 0) sh_best = idx;
    } else {
        // -------- numerator (gold path score), all smem --------
        const int* lab = labels + b * TT;
        float part = 0.f;
        for (int t = 1 + lane; t < TT; t += 32) {
            if (t < len) {
                int lt = lab[t], lp = lab[t - 1];
                part += emS[t * 32 + lt] + trS[lp * 33 + lt];
            }
        }
#pragma unroll
        for (int o = 16; o; o >>= 1) part += __shfl_xor_sync(F, part, o);
        if (lane == 0) {
            int l0 = lab[0];
            int llast = lab[len - 1];
            part += startT[l0] + emS[l0] + endT[llast];
            sh_numer = part;
        }
    }
    __syncthreads();

    if (w == 0) {
        const int last_idx = len - 1;
        const int bestl = sh_best;
        float* pred = out + 1 + (size_t)b * TT;
        for (int tt = last_idx + 1 + lane; tt < TT; tt += 32) pred[tt] = 0.0f;
        if (lane == 0) {
            d_part[b] = sh_denom - sh_numer;
            pred[last_idx] = (float)bestl;
        }
        // ---- warp-parallel backtrace via exact value matching ----
        int carry = bestl;
        float st_l = startT[lane];
        float vsp_next = ((last_idx - 1 == 0) ? st_l
                                              : bestv[(last_idx - 1) * 32 + lane]) +
                         emS[(last_idx - 1) * 32 + lane];
        for (int t = last_idx; t >= 1; t--) {
            float vsp = vsp_next;
            if (t >= 2) {
                int tm2 = t - 2;
                vsp_next = ((tm2 == 0) ? st_l : bestv[tm2 * 32 + lane]) +
                           emS[tm2 * 32 + lane];
            }
            float trv = trS[lane * 33 + carry];
            float tgt = bestv[t * 32 + carry];
            unsigned mk = __ballot_sync(F, (vsp + trv) == tgt);
            int prev = __ffs(mk) - 1;
            if (lane == 0) pred[t - 1] = (float)prev;
            carry = prev;
        }
        // ---- loss ticket reduce (replaces fin_k; R9-proven) ----
        if (lane == 0) {
            __threadfence();
            int old = atomicAdd(&d_ctr, 1);
            if (old == BB - 1) {
                __threadfence();
                float v = 0.f;   // deterministic fixed-order reduce
#pragma unroll
                for (int i = 0; i < BB; i++) v += d_part[i];
                out[0] = v;
                d_ctr = 0;       // reset for graph replay
            }
        }
    }
}

extern "C" void kernel_launch(void* const* d_in, const int* in_sizes, int n_in,
                              void* d_out, int out_size) {
    (void)in_sizes; (void)n_in; (void)out_size;
    const float* hs     = (const float*)d_in[0];
    const int*   attn   = (const int*)d_in[1];
    const int*   labels = (const int*)d_in[2];
    const float* W      = (const float*)d_in[3];
    const float* bias   = (const float*)d_in[4];
    const float* startT = (const float*)d_in[5];
    const float* endT   = (const float*)d_in[6];
    const float* trans  = (const float*)d_in[7];
    float* out = (float*)d_out;

    const int crf_smem = CRF_SMEM_FLOATS * sizeof(float);  // ~136 KB
    cudaFuncSetAttribute(crf_k, cudaFuncAttributeMaxDynamicSharedMemorySize, crf_smem);

    gemm_k<<<(BB * TT) / 128, 128>>>(hs, W, bias);
    crf_k<<<BB, 96, crf_smem>>>(attn, labels, startT, endT, trans, out);
}

// round 14
// speedup vs baseline: 4.2415x; 1.0527x over previous
#include <cuda_runtime.h>
#include <math.h>

#define BB 64
#define TT 512
#define HH 768
#define LL 32

// Scratch (static device globals: no allocation allowed)
__device__ float d_em[BB * TT * LL];    // emissions (log domain), 4 MB
__device__ float d_part[BB];            // per-batch (denom - numer)
__device__ int   d_ctr = 0;             // ticket counter for final reduce

typedef unsigned long long ull;

// ---- packed f32x2 helpers (Blackwell, PTX-only) ----
__device__ __forceinline__ ull pk2(float a, float b) {
    ull r;
    asm("mov.b64 %0, {%1, %2};" : "=l"(r) : "f"(a), "f"(b));
    return r;
}
__device__ __forceinline__ void upk2(ull v, float& a, float& b) {
    asm("mov.b64 {%0, %1}, %2;" : "=f"(a), "=f"(b) : "l"(v));
}
__device__ __forceinline__ ull f2fma(ull a, ull b, ull c) {
    ull d;
    asm("fma.rn.f32x2 %0, %1, %2, %3;" : "=l"(d) : "l"(a), "l"(b), "l"(c));
    return d;
}
__device__ __forceinline__ ull f2add(ull a, ull b) {
    ull d;
    asm("add.rn.f32x2 %0, %1, %2;" : "=l"(d) : "l"(a), "l"(b));
    return d;
}
__device__ __forceinline__ float frcp(float x) {
    float r;
    asm("rcp.approx.f32 %0, %1;" : "=f"(r) : "f"(x));
    return r;
}

// ============================================================
// Kernel 1: emissions = hidden_states @ W + b   (fp32, FFMA2)
// SINGLE-WARP blocks: 32-row x 32-col tile, 32 threads, 8x4
// per-thread tile (identical inner math / AI to the 57.5us
// config). Grid = 1024 -> 6.9 blocks/SM, wave imbalance 1.01,
// NO __syncthreads (syncwarp only). W stays L2-resident.
// ============================================================
#define KC 16
__global__ __launch_bounds__(32) void gemm_k(const float* __restrict__ hs,
                                             const float* __restrict__ W,
                                             const float* __restrict__ bias) {
    __shared__ float hsh[KC][32];
    __shared__ float wshF[KC * 32];
    const int tid = threadIdx.x;           // 0..31
    const int rowBase = blockIdx.x * 32;
    const int tr = tid >> 3, tc = tid & 7;
    const int r0 = tr * 8, c0 = tc * 4;

    ull acc[8][2];
    {
        float4 bb = *reinterpret_cast<const float4*>(bias + c0);
#pragma unroll
        for (int r = 0; r < 8; r++) {
            acc[r][0] = pk2(bb.x, bb.y);
            acc[r][1] = pk2(bb.z, bb.w);
        }
    }

    const float4* Wv4 = reinterpret_cast<const float4*>(W);
    float4 hld[4];
    float4 wld[4];

    // ---- prefetch chunk 0 ----
#pragma unroll
    for (int i = 0; i < 4; i++) {
        int idx = tid + i * 32;
        int row = idx >> 2, kq = idx & 3;
        hld[i] = *reinterpret_cast<const float4*>(hs + (size_t)(rowBase + row) * HH + kq * 4);
        wld[i] = Wv4[idx];                 // chunk0: floats W[0 .. 16*32)
    }

    const int NCH = HH / KC;  // 48
    for (int ch = 0; ch < NCH; ch++) {
        __syncwarp();
        // store current chunk to smem
#pragma unroll
        for (int i = 0; i < 4; i++) {
            int idx = tid + i * 32;
            int row = idx >> 2, kq = idx & 3;
            hsh[kq * 4 + 0][row] = hld[i].x;
            hsh[kq * 4 + 1][row] = hld[i].y;
            hsh[kq * 4 + 2][row] = hld[i].z;
            hsh[kq * 4 + 3][row] = hld[i].w;
            *reinterpret_cast<float4*>(&wshF[idx * 4]) = wld[i];
        }
        __syncwarp();

        // prefetch next chunk
        if (ch + 1 < NCH) {
            int k0 = (ch + 1) * KC;
#pragma unroll
            for (int i = 0; i < 4; i++) {
                int idx = tid + i * 32;
                int row = idx >> 2, kq = idx & 3;
                hld[i] = *reinterpret_cast<const float4*>(hs + (size_t)(rowBase + row) * HH + k0 + kq * 4);
                wld[i] = Wv4[(k0 * LL) / 4 + idx];
            }
        }

        // FMA over this chunk
#pragma unroll
        for (int kk = 0; kk < KC; kk++) {
            float4 h0 = *reinterpret_cast<const float4*>(&hsh[kk][r0]);
            float4 h1 = *reinterpret_cast<const float4*>(&hsh[kk][r0 + 4]);
            float4 w0 = *reinterpret_cast<const float4*>(&wshF[kk * 32 + c0]);
            ull wp0 = pk2(w0.x, w0.y);
            ull wp1 = pk2(w0.z, w0.w);
            float hv[8] = {h0.x, h0.y, h0.z, h0.w, h1.x, h1.y, h1.z, h1.w};
#pragma unroll
            for (int r = 0; r < 8; r++) {
                ull hv2 = pk2(hv[r], hv[r]);
                acc[r][0] = f2fma(hv2, wp0, acc[r][0]);
                acc[r][1] = f2fma(hv2, wp1, acc[r][1]);
            }
        }
    }

#pragma unroll
    for (int r = 0; r < 8; r++) {
        float a[4];
        upk2(acc[r][0], a[0], a[1]);
        upk2(acc[r][1], a[2], a[3]);
        size_t base = (size_t)(rowBase + r0 + r) * LL + c0;
        *reinterpret_cast<float4*>(d_em + base) = make_float4(a[0], a[1], a[2], a[3]);
    }
}

// ============================================================
// Kernel 2: CRF per batch (R13-exact), 1 block/batch, 3 warps:
//   warp0: forward (linear-domain) -> denom, then backtrace
//   warp1: Viterbi (max only) -> best_last
//   warp2: numerator
// Loss ticket-reduce folded in (no fin_k).
// ============================================================
#define OFF_EMS   0
#define OFF_BESTV (512 * 32)
#define OFF_TRS   (2 * 512 * 32)
#define OFF_VSH   (2 * 512 * 32 + 32 * 33)
#define CRF_SMEM_FLOATS (OFF_VSH + 128)

__global__ __launch_bounds__(96) void crf_k(const int* __restrict__ attn,
                                            const int* __restrict__ labels,
                                            const float* __restrict__ startT,
                                            const float* __restrict__ endT,
                                            const float* __restrict__ trans,
                                            float* __restrict__ out) {
    extern __shared__ float sm[];
    float* emS   = sm + OFF_EMS;
    float* bestv = sm + OFF_BESTV;
    float* trS   = sm + OFF_TRS;
    float* vshF  = sm + OFF_VSH;
    float* vshV  = sm + OFF_VSH + 64;
    __shared__ float sh_denom, sh_numer;
    __shared__ int sh_best;

    const int b = blockIdx.x;
    const int tid = threadIdx.x;
    const int w = tid >> 5, lane = tid & 31;
    const unsigned F = 0xffffffffu;

    // ---- preload emissions tile (64 KB) + transitions ----
    {
        const float4* src = reinterpret_cast<const float4*>(d_em + (size_t)b * TT * LL);
        float4* dst = reinterpret_cast<float4*>(emS);
#pragma unroll 4
        for (int i = tid; i < TT * LL / 4; i += 96) dst[i] = src[i];
        for (int idx = tid; idx < LL * LL; idx += 96)
            trS[(idx >> 5) * 33 + (idx & 31)] = trans[idx];
    }

    // sequence length (prefix mask)
    int len = 0;
    {
        const int* am = attn + b * TT;
        for (int tt = lane; tt < TT; tt += 32) len += am[tt];
#pragma unroll
        for (int o = 16; o; o >>= 1) len += __shfl_xor_sync(F, len, o);
    }
    __syncthreads();

    if (w == 0) {
        // -------- forward recursion, linear domain --------
        ull Et2[16];
#pragma unroll
        for (int q = 0; q < 16; q++)
            Et2[q] = pk2(__expf(trans[(2 * q) * LL + lane]),
                         __expf(trans[(2 * q + 1) * LL + lane]));
        float sc0 = startT[lane] + emS[lane];
        float ref0 = __shfl_sync(F, sc0, 0);
        float u = __expf(sc0 - ref0);
        float c = ref0;

        vshF[lane] = u;
        __syncwarp();

        for (int t = 1; t < len; t++) {
            float ext = __expf(emS[t * 32 + lane]);

            const ulonglong2* u2p =
                reinterpret_cast<const ulonglong2*>(&vshF[((t - 1) & 1) * 32]);
            ull s0 = 0, s1 = 0, s2 = 0, s3 = 0;
#pragma unroll
            for (int q = 0; q < 8; q += 2) {
                ulonglong2 ua = u2p[q];
                ulonglong2 ub = u2p[q + 1];
                s0 = f2fma(ua.x, Et2[2 * q], s0);
                s1 = f2fma(ua.y, Et2[2 * q + 1], s1);
                s2 = f2fma(ub.x, Et2[2 * q + 2], s2);
                s3 = f2fma(ub.y, Et2[2 * q + 3], s3);
            }
            float a0, a1, a2, a3, a4, a5, a6, a7;
            upk2(s0, a0, a1); upk2(s1, a2, a3);
            upk2(s2, a4, a5); upk2(s3, a6, a7);
            u = ext * (((a0 + a1) + (a2 + a3)) + ((a4 + a5) + (a6 + a7)));

            if ((t & 7) == 0) {
                float r = __shfl_sync(F, u, 0);
                u *= frcp(r);
                c += __logf(r);
            }
            vshF[(t & 1) * 32 + lane] = u;
            __syncwarp();
        }
        float v = u * __expf(endT[lane]);
#pragma unroll
        for (int o = 16; o; o >>= 1) v += __shfl_xor_sync(F, v, o);
        if (lane == 0) sh_denom = c + __logf(v);
    } else if (w == 1) {
        // -------- Viterbi: max only (argmax deferred to backtrace) --------
        ull tr2[16];
#pragma unroll
        for (int q = 0; q < 16; q++)
            tr2[q] = pk2(trans[(2 * q) * LL + lane], trans[(2 * q + 1) * LL + lane]);
        float vs = startT[lane] + emS[lane];
        vshV[lane] = vs;
        __syncwarp();

        for (int t = 1; t < len; t++) {
            float emt = emS[t * 32 + lane];

            const ulonglong2* v2p =
                reinterpret_cast<const ulonglong2*>(&vshV[((t - 1) & 1) * 32]);
            float m[8];
#pragma unroll
            for (int q = 0; q < 8; q++) {
                ulonglong2 uu = v2p[q];
                ull c01 = f2add(uu.x, tr2[2 * q]);
                ull c23 = f2add(uu.y, tr2[2 * q + 1]);
                float c0, c1, c2, c3;
                upk2(c01, c0, c1);
                upk2(c23, c2, c3);
                m[q] = fmaxf(fmaxf(c0, c1), fmaxf(c2, c3));
            }
            float best = fmaxf(fmaxf(fmaxf(m[0], m[1]), fmaxf(m[2], m[3])),
                               fmaxf(fmaxf(m[4], m[5]), fmaxf(m[6], m[7])));
            bestv[t * 32 + lane] = best;
            vs = best + emt;
            vshV[(t & 1) * 32 + lane] = vs;
            __syncwarp();
        }
        float v = vs + endT[lane];
        int idx = lane;
#pragma unroll
        for (int o = 16; o; o >>= 1) {
            float ov = __shfl_xor_sync(F, v, o);
            int oi = __shfl_xor_sync(F, idx, o);
            if (ov > v || (ov == v && oi < idx)) { v = ov; idx = oi; }
        }
        if (lane == 0) sh_best = idx;
    } else {
        // -------- numerator (gold path score), all smem --------
        const int* lab = labels + b * TT;
        float part = 0.f;
        for (int t = 1 + lane; t < TT; t += 32) {
            if (t < len) {
                int lt = lab[t], lp = lab[t - 1];
                part += emS[t * 32 + lt] + trS[lp * 33 + lt];
            }
        }
#pragma unroll
        for (int o = 16; o; o >>= 1) part += __shfl_xor_sync(F, part, o);
        if (lane == 0) {
            int l0 = lab[0];
            int llast = lab[len - 1];
            part += startT[l0] + emS[l0] + endT[llast];
            sh_numer = part;
        }
    }
    __syncthreads();

    if (w == 0) {
        const int last_idx = len - 1;
        const int bestl = sh_best;
        float* pred = out + 1 + (size_t)b * TT;
        for (int tt = last_idx + 1 + lane; tt < TT; tt += 32) pred[tt] = 0.0f;
        if (lane == 0) {
            d_part[b] = sh_denom - sh_numer;
            pred[last_idx] = (float)bestl;
        }
        // ---- warp-parallel backtrace via exact value matching ----
        int carry = bestl;
        float st_l = startT[lane];
        float vsp_next = ((last_idx - 1 == 0) ? st_l
                                              : bestv[(last_idx - 1) * 32 + lane]) +
                         emS[(last_idx - 1) * 32 + lane];
        for (int t = last_idx; t >= 1; t--) {
            float vsp = vsp_next;
            if (t >= 2) {
                int tm2 = t - 2;
                vsp_next = ((tm2 == 0) ? st_l : bestv[tm2 * 32 + lane]) +
                           emS[tm2 * 32 + lane];
            }
            float trv = trS[lane * 33 + carry];
            float tgt = bestv[t * 32 + carry];
            unsigned mk = __ballot_sync(F, (vsp + trv) == tgt);
            int prev = __ffs(mk) - 1;
            if (lane == 0) pred[t - 1] = (float)prev;
            carry = prev;
        }
        // ---- loss ticket reduce (replaces fin_k; R9-proven) ----
        if (lane == 0) {
            __threadfence();
            int old = atomicAdd(&d_ctr, 1);
            if (old == BB - 1) {
                __threadfence();
                float v = 0.f;   // deterministic fixed-order reduce
#pragma unroll
                for (int i = 0; i < BB; i++) v += d_part[i];
                out[0] = v;
                d_ctr = 0;       // reset for graph replay
            }
        }
    }
}

extern "C" void kernel_launch(void* const* d_in, const int* in_sizes, int n_in,
                              void* d_out, int out_size) {
    (void)in_sizes; (void)n_in; (void)out_size;
    const float* hs     = (const float*)d_in[0];
    const int*   attn   = (const int*)d_in[1];
    const int*   labels = (const int*)d_in[2];
    const float* W      = (const float*)d_in[3];
    const float* bias   = (const float*)d_in[4];
    const float* startT = (const float*)d_in[5];
    const float* endT   = (const float*)d_in[6];
    const float* trans  = (const float*)d_in[7];
    float* out = (float*)d_out;

    const int crf_smem = CRF_SMEM_FLOATS * sizeof(float);  // ~136 KB
    cudaFuncSetAttribute(crf_k, cudaFuncAttributeMaxDynamicSharedMemorySize, crf_smem);

    gemm_k<<<(BB * TT) / 32, 32>>>(hs, W, bias);
    crf_k<<<BB, 96, crf_smem>>>(attn, labels, startT, endT, trans, out);
}